// round 1
// baseline (speedup 1.0000x reference)
#include <cuda_runtime.h>

// SignedAttention: A = softmax(s*pos) - softmax(s*neg) with banded patch mask.
// B=4,H=8,L=1024,D=64; 128 patches of 8 positions; query patch p attends key
// patches p+1..p+9 only (<=72 keys). Masked logits (-10000 * 0.25) underflow
// to 0 in exp, so we compute softmax over the allowed window only. Fully
// masked rows (last patch) give A == 0 exactly -> output zeros.

constexpr int Lv   = 1024;
constexpr int Dv   = 64;
constexpr int NP   = 128;   // patches
constexpr int CH   = 8;     // positions per patch
constexpr int WIN  = 10;
constexpr int MAXK = (WIN - 1) * CH;   // 72 keys max
constexpr int KP   = 76;    // k smem pitch (floats): 304B rows, 16B aligned,
                            // float4 bank phase (3j+i)%8 -> conflict-free
constexpr int NT   = 512;

__global__ __launch_bounds__(NT, 1)
void signed_attn_kernel(const float* __restrict__ Q,
                        const float* __restrict__ K,
                        const float* __restrict__ V,
                        const float* __restrict__ LS,
                        float* __restrict__ O)
{
    __shared__ float qs[CH][Dv];          // 2 KB
    __shared__ float ks[MAXK][KP];        // 21.4 KB
    __shared__ float vs[MAXK][Dv];        // 18 KB
    __shared__ float attn[CH][MAXK + 8];  // 2.5 KB (scores, then weights)

    const int bh  = blockIdx.x / NP;
    const int p   = blockIdx.x % NP;
    const int tid = threadIdx.x;

    const size_t qbase = ((size_t)bh * Lv + (size_t)p * CH) * Dv; // 512 floats per tile

    const int npk = min(WIN - 1, NP - 1 - p);
    const int nk  = npk * CH;             // multiple of 8, 0..72

    if (nk == 0) {                        // last patch: fully masked -> A == 0
        O[qbase + tid] = 0.0f;
        return;
    }

    const float scale = fminf(fmaxf(expf(LS[0]), 1.0f), 30.0f) * 0.125f; // /sqrt(64)

    // ---- load Q tile (8x64 = 128 float4) ----
    if (tid < (CH * Dv) / 4) {
        ((float4*)&qs[0][0])[tid] = ((const float4*)(Q + qbase))[tid];
    }

    // ---- load K/V window ( nk x 64 ) ----
    {
        const size_t kbase = ((size_t)bh * Lv + (size_t)(p + 1) * CH) * Dv;
        const float4* Kg = (const float4*)(K + kbase);
        const float4* Vg = (const float4*)(V + kbase);
        const int n4 = nk * (Dv / 4);      // up to 1152 float4 per tensor
        for (int idx = tid; idx < n4; idx += NT) {
            int r = idx >> 4;              // key row
            int c = idx & 15;              // float4 column
            *(float4*)&ks[r][c * 4] = Kg[idx];
            *(float4*)&vs[r][c * 4] = Vg[idx];
        }
    }
    __syncthreads();

    // ---- phase 1: scores[q][j] = scale * q . k ----
    for (int s = tid; s < CH * MAXK; s += NT) {
        int q = s / MAXK;
        int j = s - q * MAXK;
        if (j < nk) {
            const float4* qr = (const float4*)qs[q];
            float acc = 0.0f;
            #pragma unroll
            for (int i = 0; i < Dv / 4; i++) {
                float4 a = qr[i];
                float4 b = *(const float4*)&ks[j][4 * i];
                acc = fmaf(a.x, b.x, acc);
                acc = fmaf(a.y, b.y, acc);
                acc = fmaf(a.z, b.z, acc);
                acc = fmaf(a.w, b.w, acc);
            }
            attn[q][j] = scale * acc;
        }
    }
    __syncthreads();

    // ---- phase 2: dual softmax per query row (warp w handles q = w) ----
    const int w    = tid >> 5;
    const int lane = tid & 31;
    if (w < CH) {
        float mx = -1e30f, mn = 1e30f;
        for (int j = lane; j < nk; j += 32) {
            float t = attn[w][j];
            mx = fmaxf(mx, t);
            mn = fminf(mn, t);
        }
        #pragma unroll
        for (int o = 16; o; o >>= 1) {
            mx = fmaxf(mx, __shfl_xor_sync(0xffffffffu, mx, o));
            mn = fminf(mn, __shfl_xor_sync(0xffffffffu, mn, o));
        }
        float sp = 0.0f, sn = 0.0f;        // sum exp(t-mx), sum exp(-t - (-mn))
        for (int j = lane; j < nk; j += 32) {
            float t = attn[w][j];
            sp += __expf(t - mx);
            sn += __expf(mn - t);
        }
        #pragma unroll
        for (int o = 16; o; o >>= 1) {
            sp += __shfl_xor_sync(0xffffffffu, sp, o);
            sn += __shfl_xor_sync(0xffffffffu, sn, o);
        }
        const float rp = 1.0f / sp;
        const float rn = 1.0f / sn;
        for (int j = lane; j < nk; j += 32) {
            float t = attn[w][j];
            attn[w][j] = __expf(t - mx) * rp - __expf(mn - t) * rn;
        }
    }
    __syncthreads();

    // ---- phase 3: out[q][d] = sum_j attn[q][j] * v[j][d] ----
    {
        const int q = tid >> 6;            // 0..7
        const int d = tid & 63;
        float acc = 0.0f;
        #pragma unroll 4
        for (int j = 0; j < nk; j++) {
            acc = fmaf(attn[q][j], vs[j][d], acc);
        }
        O[qbase + tid] = acc;
    }
}

extern "C" void kernel_launch(void* const* d_in, const int* in_sizes, int n_in,
                              void* d_out, int out_size)
{
    const float* Q  = (const float*)d_in[0];
    const float* K  = (const float*)d_in[1];
    const float* V  = (const float*)d_in[2];
    const float* LS = (const float*)d_in[3];
    float* O = (float*)d_out;

    const int BH = in_sizes[0] / (Lv * Dv);   // B*H = 32
    signed_attn_kernel<<<BH * NP, NT>>>(Q, K, V, LS, O);
}

// round 2
// speedup vs baseline: 1.2033x; 1.2033x over previous
#include <cuda_runtime.h>

// SignedAttention, R2: register-blocked, broadcast-aware smem traffic.
// B=4,H=8,L=1024,D=64; 128 patches of 8; query patch p attends key patches
// p+1..p+9 (<=72 keys). Masked logits underflow to 0 in exp -> windowed
// softmax; last patch fully masked -> A == 0.

constexpr int Lv   = 1024;
constexpr int Dv   = 64;
constexpr int NP   = 128;
constexpr int CH   = 8;
constexpr int MAXK = 72;
constexpr int KP   = 76;   // K pitch: quad stride 19 (odd) -> conflict-free column reads
constexpr int AP   = 12;   // attn pitch: 48B rows, 16B aligned, quad stride 3 -> CF stores
constexpr int NT   = 256;

__global__ __launch_bounds__(NT, 1)
void signed_attn_kernel(const float* __restrict__ Q,
                        const float* __restrict__ K,
                        const float* __restrict__ V,
                        const float* __restrict__ LS,
                        float* __restrict__ O)
{
    __shared__ float qs[CH][Dv];          // 2 KB
    __shared__ float ks[MAXK][KP];        // 21.4 KB
    __shared__ float vs[MAXK][Dv];        // 18 KB
    __shared__ float at[MAXK][AP];        // 3.4 KB : scores then weights, [key][query]

    const int bh   = blockIdx.x / NP;
    const int p    = blockIdx.x % NP;
    const int tid  = threadIdx.x;
    const int warp = tid >> 5;
    const int lane = tid & 31;

    const size_t qbase = ((size_t)bh * Lv + (size_t)p * CH) * Dv;  // 512 floats

    const int npk = min(9, NP - 1 - p);
    const int nk  = npk * CH;             // multiple of 8, 0..72

    if (nk == 0) {                        // last patch: A == 0 exactly
        O[qbase + tid]      = 0.0f;
        O[qbase + tid + NT] = 0.0f;
        return;
    }

    const float scale = fminf(fmaxf(expf(LS[0]), 1.0f), 30.0f) * 0.125f;

    // ---- stage Q, K, V ----
    if (tid < (CH * Dv) / 4) {
        ((float4*)&qs[0][0])[tid] = ((const float4*)(Q + qbase))[tid];
    }
    {
        const size_t kbase = ((size_t)bh * Lv + (size_t)(p + 1) * CH) * Dv;
        const float4* Kg = (const float4*)(K + kbase);
        const float4* Vg = (const float4*)(V + kbase);
        const int n4 = nk * (Dv / 4);
        for (int idx = tid; idx < n4; idx += NT) {
            int r = idx >> 4;
            int c = idx & 15;
            *(float4*)&ks[r][c * 4] = Kg[idx];
            *(float4*)&vs[r][c * 4] = Vg[idx];
        }
    }
    __syncthreads();

    // ---- phase 1: lane = key j, accumulate scores for all 8 queries ----
    // K row read conflict-free; 8 Q reads per d-chunk are warp-broadcast.
    if (warp < 3) {
        const int j = warp * 32 + lane;
        if (j < nk) {
            float acc[CH] = {0,0,0,0,0,0,0,0};
            #pragma unroll
            for (int dd = 0; dd < Dv / 4; dd++) {
                const float4 kf = *(const float4*)&ks[j][dd * 4];
                #pragma unroll
                for (int qi = 0; qi < CH; qi++) {
                    const float4 qf = *(const float4*)&qs[qi][dd * 4];
                    acc[qi] = fmaf(qf.x, kf.x, acc[qi]);
                    acc[qi] = fmaf(qf.y, kf.y, acc[qi]);
                    acc[qi] = fmaf(qf.z, kf.z, acc[qi]);
                    acc[qi] = fmaf(qf.w, kf.w, acc[qi]);
                }
            }
            float4 s0 = make_float4(acc[0]*scale, acc[1]*scale, acc[2]*scale, acc[3]*scale);
            float4 s1 = make_float4(acc[4]*scale, acc[5]*scale, acc[6]*scale, acc[7]*scale);
            *(float4*)&at[j][0] = s0;
            *(float4*)&at[j][4] = s1;
        }
    }
    __syncthreads();

    // ---- phase 2: warp q -> dual softmax over row q; scores cached in regs ----
    {
        const int q = warp;
        const bool v0 = (lane      < nk);
        const bool v1 = (lane + 32 < nk);
        const bool v2 = (lane + 64 < nk);
        const float t0 = v0 ? at[lane     ][q] : 0.0f;
        const float t1 = v1 ? at[lane + 32][q] : 0.0f;
        const float t2 = v2 ? at[lane + 64][q] : 0.0f;

        float mx = -1e30f, mn = 1e30f;
        if (v0) { mx = fmaxf(mx, t0); mn = fminf(mn, t0); }
        if (v1) { mx = fmaxf(mx, t1); mn = fminf(mn, t1); }
        if (v2) { mx = fmaxf(mx, t2); mn = fminf(mn, t2); }
        #pragma unroll
        for (int o = 16; o; o >>= 1) {
            mx = fmaxf(mx, __shfl_xor_sync(0xffffffffu, mx, o));
            mn = fminf(mn, __shfl_xor_sync(0xffffffffu, mn, o));
        }

        float sp = 0.0f, sn = 0.0f;
        float e0p=0, e0n=0, e1p=0, e1n=0, e2p=0, e2n=0;
        if (v0) { e0p = __expf(t0 - mx); e0n = __expf(mn - t0); sp += e0p; sn += e0n; }
        if (v1) { e1p = __expf(t1 - mx); e1n = __expf(mn - t1); sp += e1p; sn += e1n; }
        if (v2) { e2p = __expf(t2 - mx); e2n = __expf(mn - t2); sp += e2p; sn += e2n; }
        #pragma unroll
        for (int o = 16; o; o >>= 1) {
            sp += __shfl_xor_sync(0xffffffffu, sp, o);
            sn += __shfl_xor_sync(0xffffffffu, sn, o);
        }
        const float rp = 1.0f / sp;
        const float rn = 1.0f / sn;
        if (v0) at[lane     ][q] = e0p * rp - e0n * rn;
        if (v1) at[lane + 32][q] = e1p * rp - e1n * rn;
        if (v2) at[lane + 64][q] = e2p * rp - e2n * rn;
    }
    __syncthreads();

    // ---- phase 3: warp w owns d in [16w,16w+16); lane = (q, d-quad) ----
    // at[j][0..7] merges to 1 wavefront; v[j][16w..16w+16) merges to 64B.
    if (warp < 4) {
        const int q   = lane >> 2;
        const int dof = warp * 16 + (lane & 3) * 4;
        float4 acc = make_float4(0.f, 0.f, 0.f, 0.f);
        #pragma unroll 4
        for (int j = 0; j < nk; j++) {
            const float a = at[j][q];
            const float4 vv = *(const float4*)&vs[j][dof];
            acc.x = fmaf(a, vv.x, acc.x);
            acc.y = fmaf(a, vv.y, acc.y);
            acc.z = fmaf(a, vv.z, acc.z);
            acc.w = fmaf(a, vv.w, acc.w);
        }
        *(float4*)(O + qbase + (size_t)q * Dv + dof) = acc;
    }
}

extern "C" void kernel_launch(void* const* d_in, const int* in_sizes, int n_in,
                              void* d_out, int out_size)
{
    const float* Q  = (const float*)d_in[0];
    const float* K  = (const float*)d_in[1];
    const float* V  = (const float*)d_in[2];
    const float* LS = (const float*)d_in[3];
    float* O = (float*)d_out;

    const int BH = in_sizes[0] / (Lv * Dv);   // B*H = 32
    signed_attn_kernel<<<BH * NP, NT>>>(Q, K, V, LS, O);
}

// round 3
// speedup vs baseline: 1.4299x; 1.1882x over previous
#include <cuda_runtime.h>
#include <cstdint>

// SignedAttention R3: cp.async staging, 4-CTA occupancy, all-warp phases.
// B=4,H=8,L=1024,D=64; 128 patches of 8; query patch p attends key patches
// p+1..p+9 (<=72 keys). Masked logits underflow to 0 in exp -> windowed
// softmax; last patch fully masked -> A == 0 exactly.

constexpr int Lv   = 1024;
constexpr int Dv   = 64;
constexpr int NP   = 128;
constexpr int CH   = 8;
constexpr int MAXK = 72;
constexpr int KP   = 76;   // K pitch: 16B-quad stride 19 -> conflict-free rows
constexpr int AP   = 12;   // attn pitch: quad stride 3 -> CF float4 stores
constexpr int NT   = 256;

__device__ __forceinline__ void cp16(void* dst, const void* src) {
    uint32_t d = (uint32_t)__cvta_generic_to_shared(dst);
    asm volatile("cp.async.cg.shared.global [%0], [%1], 16;" :: "r"(d), "l"(src));
}
__device__ __forceinline__ void cp_commit() {
    asm volatile("cp.async.commit_group;");
}
__device__ __forceinline__ void cp_wait1() {
    asm volatile("cp.async.wait_group 1;");
}
__device__ __forceinline__ void cp_wait0() {
    asm volatile("cp.async.wait_group 0;");
}

__global__ __launch_bounds__(NT, 4)
void signed_attn_kernel(const float* __restrict__ Q,
                        const float* __restrict__ K,
                        const float* __restrict__ V,
                        const float* __restrict__ LS,
                        float* __restrict__ O)
{
    __shared__ float qs[CH][Dv];          // 2 KB
    __shared__ float ks[MAXK][KP];        // 21.4 KB
    __shared__ float vs[MAXK][Dv];        // 18 KB
    __shared__ float at[MAXK][AP];        // 3.4 KB : scores then weights, [key][query]

    const int bh   = blockIdx.x / NP;
    const int p    = blockIdx.x % NP;
    const int tid  = threadIdx.x;
    const int warp = tid >> 5;
    const int lane = tid & 31;

    const size_t qbase = ((size_t)bh * Lv + (size_t)p * CH) * Dv;  // 512 floats

    const int npk = min(9, NP - 1 - p);
    const int nk  = npk * CH;             // multiple of 8, 0..72

    if (nk == 0) {                        // last patch: A == 0 exactly
        O[qbase + tid]      = 0.0f;
        O[qbase + tid + NT] = 0.0f;
        return;
    }

    // ---- stage via cp.async: group1 = Q+K, group2 = V ----
    const size_t kbase = ((size_t)bh * Lv + (size_t)(p + 1) * CH) * Dv;
    const int n4 = nk * (Dv / 4);         // up to 1152 quads
    {
        if (tid < (CH * Dv) / 4) {
            int r = tid >> 4, c = tid & 15;
            cp16(&qs[r][c * 4], (const float4*)(Q + qbase) + tid);
        }
        const float4* Kg = (const float4*)(K + kbase);
        for (int idx = tid; idx < n4; idx += NT) {
            int r = idx >> 4, c = idx & 15;
            cp16(&ks[r][c * 4], Kg + idx);
        }
        cp_commit();
        const float4* Vg = (const float4*)(V + kbase);
        for (int idx = tid; idx < n4; idx += NT) {
            int r = idx >> 4, c = idx & 15;
            cp16(&vs[r][c * 4], Vg + idx);
        }
        cp_commit();
    }

    const float scale = fminf(fmaxf(expf(LS[0]), 1.0f), 30.0f) * 0.125f;

    cp_wait1();                            // Q + K ready, V still in flight
    __syncthreads();

    // ---- phase 1: 6 warps, lane = key, 4-query accumulator halves ----
    if (warp < 6) {
        const int half = (warp >= 3) ? 1 : 0;          // q 0-3 or q 4-7
        const int j    = (warp - 3 * half) * 32 + lane;
        if (j < nk) {
            const int qo = half * 4;
            float a0 = 0.f, a1 = 0.f, a2 = 0.f, a3 = 0.f;
            #pragma unroll
            for (int dd = 0; dd < Dv / 4; dd++) {
                const float4 kf = *(const float4*)&ks[j][dd * 4];
                float4 qf;
                qf = *(const float4*)&qs[qo + 0][dd * 4];
                a0 = fmaf(qf.x, kf.x, a0); a0 = fmaf(qf.y, kf.y, a0);
                a0 = fmaf(qf.z, kf.z, a0); a0 = fmaf(qf.w, kf.w, a0);
                qf = *(const float4*)&qs[qo + 1][dd * 4];
                a1 = fmaf(qf.x, kf.x, a1); a1 = fmaf(qf.y, kf.y, a1);
                a1 = fmaf(qf.z, kf.z, a1); a1 = fmaf(qf.w, kf.w, a1);
                qf = *(const float4*)&qs[qo + 2][dd * 4];
                a2 = fmaf(qf.x, kf.x, a2); a2 = fmaf(qf.y, kf.y, a2);
                a2 = fmaf(qf.z, kf.z, a2); a2 = fmaf(qf.w, kf.w, a2);
                qf = *(const float4*)&qs[qo + 3][dd * 4];
                a3 = fmaf(qf.x, kf.x, a3); a3 = fmaf(qf.y, kf.y, a3);
                a3 = fmaf(qf.z, kf.z, a3); a3 = fmaf(qf.w, kf.w, a3);
            }
            *(float4*)&at[j][qo] =
                make_float4(a0 * scale, a1 * scale, a2 * scale, a3 * scale);
        }
    }
    __syncthreads();

    // ---- phase 2: warp q -> dual softmax over row q; scores in regs ----
    {
        const int q = warp;
        const bool v0 = (lane      < nk);
        const bool v1 = (lane + 32 < nk);
        const bool v2 = (lane + 64 < nk);
        const float t0 = v0 ? at[lane     ][q] : 0.0f;
        const float t1 = v1 ? at[lane + 32][q] : 0.0f;
        const float t2 = v2 ? at[lane + 64][q] : 0.0f;

        float mx = -1e30f, mn = 1e30f;
        if (v0) { mx = fmaxf(mx, t0); mn = fminf(mn, t0); }
        if (v1) { mx = fmaxf(mx, t1); mn = fminf(mn, t1); }
        if (v2) { mx = fmaxf(mx, t2); mn = fminf(mn, t2); }
        #pragma unroll
        for (int o = 16; o; o >>= 1) {
            mx = fmaxf(mx, __shfl_xor_sync(0xffffffffu, mx, o));
            mn = fminf(mn, __shfl_xor_sync(0xffffffffu, mn, o));
        }

        float sp = 0.0f, sn = 0.0f;
        float e0p=0, e0n=0, e1p=0, e1n=0, e2p=0, e2n=0;
        if (v0) { e0p = __expf(t0 - mx); e0n = __expf(mn - t0); sp += e0p; sn += e0n; }
        if (v1) { e1p = __expf(t1 - mx); e1n = __expf(mn - t1); sp += e1p; sn += e1n; }
        if (v2) { e2p = __expf(t2 - mx); e2n = __expf(mn - t2); sp += e2p; sn += e2n; }
        #pragma unroll
        for (int o = 16; o; o >>= 1) {
            sp += __shfl_xor_sync(0xffffffffu, sp, o);
            sn += __shfl_xor_sync(0xffffffffu, sn, o);
        }
        const float rp = 1.0f / sp;
        const float rn = 1.0f / sn;
        if (v0) at[lane     ][q] = e0p * rp - e0n * rn;
        if (v1) at[lane + 32][q] = e1p * rp - e1n * rn;
        if (v2) at[lane + 64][q] = e2p * rp - e2n * rn;
    }
    cp_wait0();                            // V ready
    __syncthreads();

    // ---- phase 3: all 8 warps; warp w owns d in [8w, 8w+8); lane=(q,dpair) ----
    // at[j][q] broadcast (1 wf); v[j][8w..8w+8) merges to 32B (1 wf).
    {
        const int q   = lane >> 2;
        const int dof = warp * 8 + (lane & 3) * 2;
        float2 acc = make_float2(0.f, 0.f);
        #pragma unroll 4
        for (int j = 0; j < nk; j++) {
            const float a = at[j][q];
            const float2 vv = *(const float2*)&vs[j][dof];
            acc.x = fmaf(a, vv.x, acc.x);
            acc.y = fmaf(a, vv.y, acc.y);
        }
        *(float2*)(O + qbase + (size_t)q * Dv + dof) = acc;
    }
}

extern "C" void kernel_launch(void* const* d_in, const int* in_sizes, int n_in,
                              void* d_out, int out_size)
{
    const float* Q  = (const float*)d_in[0];
    const float* K  = (const float*)d_in[1];
    const float* V  = (const float*)d_in[2];
    const float* LS = (const float*)d_in[3];
    float* O = (float*)d_out;

    const int BH = in_sizes[0] / (Lv * Dv);   // B*H = 32
    signed_attn_kernel<<<BH * NP, NT>>>(Q, K, V, LS, O);
}

// round 4
// speedup vs baseline: 1.5517x; 1.0852x over previous
#include <cuda_runtime.h>
#include <cstdint>

// SignedAttention R4: d-split phase1 (no duplicate K reads), conflict-free
// attn pitch 9, key-split phase3 with 16-wide d slices + smem partial reduce.

constexpr int Lv   = 1024;
constexpr int Dv   = 64;
constexpr int NP   = 128;
constexpr int CH   = 8;
constexpr int MAXK = 72;
constexpr int KP   = 76;   // K pitch: quad stride 19 -> conflict-free row reads
constexpr int AP   = 9;    // attn pitch: gcd(9,32)=1 -> CF for lane*9+q scalar access
constexpr int NT   = 256;

__device__ __forceinline__ void cp16(void* dst, const void* src) {
    uint32_t d = (uint32_t)__cvta_generic_to_shared(dst);
    asm volatile("cp.async.cg.shared.global [%0], [%1], 16;" :: "r"(d), "l"(src));
}
__device__ __forceinline__ void cp_commit() { asm volatile("cp.async.commit_group;"); }
__device__ __forceinline__ void cp_wait1()  { asm volatile("cp.async.wait_group 1;"); }
__device__ __forceinline__ void cp_wait0()  { asm volatile("cp.async.wait_group 0;"); }

__global__ __launch_bounds__(NT, 4)
void signed_attn_kernel(const float* __restrict__ Q,
                        const float* __restrict__ K,
                        const float* __restrict__ V,
                        const float* __restrict__ LS,
                        float* __restrict__ O)
{
    __shared__ float qs[CH][Dv];           // 2 KB
    __shared__ float ks[MAXK][KP];         // 21.4 KB
    __shared__ float vs[MAXK][Dv];         // 18 KB
    __shared__ float at2[2][MAXK][AP];     // 5.1 KB : score halves, then weights in [0]
    __shared__ float part[CH][Dv];         // 2 KB  : phase-3 partial sums

    const int bh   = blockIdx.x / NP;
    const int p    = blockIdx.x % NP;
    const int tid  = threadIdx.x;
    const int warp = tid >> 5;
    const int lane = tid & 31;

    const size_t qbase = ((size_t)bh * Lv + (size_t)p * CH) * Dv;

    const int npk = min(9, NP - 1 - p);
    const int nk  = npk * CH;              // multiple of 8, 0..72

    if (nk == 0) {                         // last patch: A == 0 exactly
        O[qbase + tid]      = 0.0f;
        O[qbase + tid + NT] = 0.0f;
        return;
    }

    // ---- stage via cp.async: group1 = Q+K, group2 = V ----
    const size_t kbase = ((size_t)bh * Lv + (size_t)(p + 1) * CH) * Dv;
    const int n4 = nk * (Dv / 4);
    {
        if (tid < (CH * Dv) / 4) {
            int r = tid >> 4, c = tid & 15;
            cp16(&qs[r][c * 4], (const float4*)(Q + qbase) + tid);
        }
        const float4* Kg = (const float4*)(K + kbase);
        for (int idx = tid; idx < n4; idx += NT) {
            int r = idx >> 4, c = idx & 15;
            cp16(&ks[r][c * 4], Kg + idx);
        }
        cp_commit();
        const float4* Vg = (const float4*)(V + kbase);
        for (int idx = tid; idx < n4; idx += NT) {
            int r = idx >> 4, c = idx & 15;
            cp16(&vs[r][c * 4], Vg + idx);
        }
        cp_commit();
    }

    const float scale = fminf(fmaxf(expf(LS[0]), 1.0f), 30.0f) * 0.125f;

    cp_wait1();                            // Q + K ready, V still in flight
    __syncthreads();

    // ---- phase 1: 6 warps = (3 key-groups) x (2 d-halves), acc over 8 q ----
    if (warp < 6) {
        const int h  = (warp >= 3) ? 1 : 0;            // d-half
        const int j  = (warp - 3 * h) * 32 + lane;     // key
        if (j < nk) {
            const int db = h * 8;                      // dd base (8 quads = 32 dims)
            float acc[CH] = {0,0,0,0,0,0,0,0};
            #pragma unroll
            for (int dd = 0; dd < 8; dd++) {
                const float4 kf = *(const float4*)&ks[j][(db + dd) * 4];
                #pragma unroll
                for (int qi = 0; qi < CH; qi++) {
                    const float4 qf = *(const float4*)&qs[qi][(db + dd) * 4];
                    acc[qi] = fmaf(qf.x, kf.x, acc[qi]);
                    acc[qi] = fmaf(qf.y, kf.y, acc[qi]);
                    acc[qi] = fmaf(qf.z, kf.z, acc[qi]);
                    acc[qi] = fmaf(qf.w, kf.w, acc[qi]);
                }
            }
            #pragma unroll
            for (int qi = 0; qi < CH; qi++)            // pitch-9 scalar: CF
                at2[h][j][qi] = acc[qi];
        }
    }
    __syncthreads();

    // ---- phase 2: warp q -> dual softmax over row q (adds d-halves) ----
    {
        const int q = warp;
        const bool v0 = (lane      < nk);
        const bool v1 = (lane + 32 < nk);
        const bool v2 = (lane + 64 < nk);
        const float t0 = v0 ? (at2[0][lane     ][q] + at2[1][lane     ][q]) * scale : 0.0f;
        const float t1 = v1 ? (at2[0][lane + 32][q] + at2[1][lane + 32][q]) * scale : 0.0f;
        const float t2 = v2 ? (at2[0][lane + 64][q] + at2[1][lane + 64][q]) * scale : 0.0f;

        float mx = -1e30f, mn = 1e30f;
        if (v0) { mx = fmaxf(mx, t0); mn = fminf(mn, t0); }
        if (v1) { mx = fmaxf(mx, t1); mn = fminf(mn, t1); }
        if (v2) { mx = fmaxf(mx, t2); mn = fminf(mn, t2); }
        #pragma unroll
        for (int o = 16; o; o >>= 1) {
            mx = fmaxf(mx, __shfl_xor_sync(0xffffffffu, mx, o));
            mn = fminf(mn, __shfl_xor_sync(0xffffffffu, mn, o));
        }

        float sp = 0.0f, sn = 0.0f;
        float e0p=0, e0n=0, e1p=0, e1n=0, e2p=0, e2n=0;
        if (v0) { e0p = __expf(t0 - mx); e0n = __expf(mn - t0); sp += e0p; sn += e0n; }
        if (v1) { e1p = __expf(t1 - mx); e1n = __expf(mn - t1); sp += e1p; sn += e1n; }
        if (v2) { e2p = __expf(t2 - mx); e2n = __expf(mn - t2); sp += e2p; sn += e2n; }
        #pragma unroll
        for (int o = 16; o; o >>= 1) {
            sp += __shfl_xor_sync(0xffffffffu, sp, o);
            sn += __shfl_xor_sync(0xffffffffu, sn, o);
        }
        const float rp = 1.0f / sp;
        const float rn = 1.0f / sn;
        if (v0) at2[0][lane     ][q] = e0p * rp - e0n * rn;
        if (v1) at2[0][lane + 32][q] = e1p * rp - e1n * rn;
        if (v2) at2[0][lane + 64][q] = e2p * rp - e2n * rn;
    }
    cp_wait0();                            // V ready
    __syncthreads();

    // ---- phase 3: key-split halves x 16-wide d slices ----
    // warp w (0-3): keys [0, nk/2), d slice 16w; warp w (4-7): keys [nk/2, nk).
    {
        const int w4   = warp & 3;
        const int q    = lane >> 2;                     // 0..7
        const int dof  = w4 * 16 + (lane & 3) * 4;      // float4 slice
        const int half = nk >> 1;                       // multiple of 4
        const int j0   = (warp >= 4) ? half : 0;
        const int j1   = (warp >= 4) ? nk   : half;

        float4 acc = make_float4(0.f, 0.f, 0.f, 0.f);
        #pragma unroll 4
        for (int j = j0; j < j1; j++) {
            const float a = at2[0][j][q];               // 8 distinct, broadcast: 1 wf
            const float4 vv = *(const float4*)&vs[j][dof];  // 64B: 1 wf
            acc.x = fmaf(a, vv.x, acc.x);
            acc.y = fmaf(a, vv.y, acc.y);
            acc.z = fmaf(a, vv.z, acc.z);
            acc.w = fmaf(a, vv.w, acc.w);
        }
        if (warp >= 4)
            *(float4*)&part[q][dof] = acc;
        __syncthreads();
        if (warp < 4) {
            const float4 pp = *(const float4*)&part[q][dof];
            acc.x += pp.x; acc.y += pp.y; acc.z += pp.z; acc.w += pp.w;
            *(float4*)(O + qbase + (size_t)q * Dv + dof) = acc;
        }
    }
}

extern "C" void kernel_launch(void* const* d_in, const int* in_sizes, int n_in,
                              void* d_out, int out_size)
{
    const float* Q  = (const float*)d_in[0];
    const float* K  = (const float*)d_in[1];
    const float* V  = (const float*)d_in[2];
    const float* LS = (const float*)d_in[3];
    float* O = (float*)d_out;

    const int BH = in_sizes[0] / (Lv * Dv);   // B*H = 32
    signed_attn_kernel<<<BH * NP, NT>>>(Q, K, V, LS, O);
}

// round 5
// speedup vs baseline: 1.5953x; 1.0281x over previous
#include <cuda_runtime.h>
#include <cstdint>

// SignedAttention R5: 2-warp phase1 (Q-broadcasts 384->128 wf), transposed
// attention weights for float4 phase-3 A loads (288->72 wf).

constexpr int Lv   = 1024;
constexpr int Dv   = 64;
constexpr int NP   = 128;
constexpr int CH   = 8;
constexpr int MAXK = 72;
constexpr int KP   = 76;   // K pitch: quad stride 19 -> conflict-free row reads
constexpr int AP   = 9;    // score pitch: gcd(9,32)=1 -> CF scalar access
constexpr int TP   = 76;   // at_t pitch: 12q mod 32 distinct -> CF quad reads
constexpr int NT   = 256;

__device__ __forceinline__ void cp16(void* dst, const void* src) {
    uint32_t d = (uint32_t)__cvta_generic_to_shared(dst);
    asm volatile("cp.async.cg.shared.global [%0], [%1], 16;" :: "r"(d), "l"(src));
}
__device__ __forceinline__ void cp_commit() { asm volatile("cp.async.commit_group;"); }
__device__ __forceinline__ void cp_wait1()  { asm volatile("cp.async.wait_group 1;"); }
__device__ __forceinline__ void cp_wait0()  { asm volatile("cp.async.wait_group 0;"); }

__global__ __launch_bounds__(NT, 4)
void signed_attn_kernel(const float* __restrict__ Q,
                        const float* __restrict__ K,
                        const float* __restrict__ V,
                        const float* __restrict__ LS,
                        float* __restrict__ O)
{
    __shared__ float qs[CH][Dv];           // 2 KB
    __shared__ float ks[MAXK][KP];         // 21.4 KB
    __shared__ float vs[MAXK][Dv];         // 18 KB
    __shared__ float at2[2][MAXK][AP];     // 5.1 KB : raw score halves
    __shared__ float at_t[CH][TP];         // 2.4 KB : softmaxed weights, [q][key]
    __shared__ float part[CH][Dv];         // 2 KB  : phase-3 partials

    const int bh   = blockIdx.x / NP;
    const int p    = blockIdx.x % NP;
    const int tid  = threadIdx.x;
    const int warp = tid >> 5;
    const int lane = tid & 31;

    const size_t qbase = ((size_t)bh * Lv + (size_t)p * CH) * Dv;

    const int npk = min(9, NP - 1 - p);
    const int nk  = npk * CH;              // multiple of 8, 0..72

    if (nk == 0) {                         // last patch: A == 0 exactly
        O[qbase + tid]      = 0.0f;
        O[qbase + tid + NT] = 0.0f;
        return;
    }

    // ---- stage via cp.async: group1 = Q+K, group2 = V ----
    const size_t kbase = ((size_t)bh * Lv + (size_t)(p + 1) * CH) * Dv;
    const int n4 = nk * (Dv / 4);
    {
        if (tid < (CH * Dv) / 4) {
            int r = tid >> 4, c = tid & 15;
            cp16(&qs[r][c * 4], (const float4*)(Q + qbase) + tid);
        }
        const float4* Kg = (const float4*)(K + kbase);
        for (int idx = tid; idx < n4; idx += NT) {
            int r = idx >> 4, c = idx & 15;
            cp16(&ks[r][c * 4], Kg + idx);
        }
        cp_commit();
        const float4* Vg = (const float4*)(V + kbase);
        for (int idx = tid; idx < n4; idx += NT) {
            int r = idx >> 4, c = idx & 15;
            cp16(&vs[r][c * 4], Vg + idx);
        }
        cp_commit();
    }

    const float scale = fminf(fmaxf(expf(LS[0]), 1.0f), 30.0f) * 0.125f;

    cp_wait1();                            // Q + K ready, V still in flight
    __syncthreads();

    // ---- phase 1: warp h (0,1) = d-half h; lane covers keys {l, l+32, l+64} ----
    if (warp < 2) {
        const int db = warp * 8;           // dd base (8 quads = 32 dims)
        const bool p0 = (lane      < nk);
        const bool p1 = (lane + 32 < nk);
        const bool p2 = (lane + 64 < nk);
        const int  j0 = lane;
        const int  j1 = p1 ? lane + 32 : 0;      // clamp (safe smem index)
        const int  j2 = p2 ? lane + 64 : 0;

        float acc[3 * CH];
        #pragma unroll
        for (int i = 0; i < 3 * CH; i++) acc[i] = 0.0f;

        #pragma unroll
        for (int dd = 0; dd < 8; dd++) {
            const int c = (db + dd) * 4;
            const float4 k0 = *(const float4*)&ks[j0][c];
            const float4 k1 = *(const float4*)&ks[j1][c];
            const float4 k2 = *(const float4*)&ks[j2][c];
            #pragma unroll
            for (int qi = 0; qi < CH; qi++) {
                const float4 qf = *(const float4*)&qs[qi][c];
                float a0 = acc[qi * 3 + 0];
                float a1 = acc[qi * 3 + 1];
                float a2 = acc[qi * 3 + 2];
                a0 = fmaf(qf.x, k0.x, a0); a1 = fmaf(qf.x, k1.x, a1); a2 = fmaf(qf.x, k2.x, a2);
                a0 = fmaf(qf.y, k0.y, a0); a1 = fmaf(qf.y, k1.y, a1); a2 = fmaf(qf.y, k2.y, a2);
                a0 = fmaf(qf.z, k0.z, a0); a1 = fmaf(qf.z, k1.z, a1); a2 = fmaf(qf.z, k2.z, a2);
                a0 = fmaf(qf.w, k0.w, a0); a1 = fmaf(qf.w, k1.w, a1); a2 = fmaf(qf.w, k2.w, a2);
                acc[qi * 3 + 0] = a0;
                acc[qi * 3 + 1] = a1;
                acc[qi * 3 + 2] = a2;
            }
        }
        #pragma unroll
        for (int qi = 0; qi < CH; qi++) {
            if (p0) at2[warp][j0][qi] = acc[qi * 3 + 0];
            if (p1) at2[warp][j1][qi] = acc[qi * 3 + 1];
            if (p2) at2[warp][j2][qi] = acc[qi * 3 + 2];
        }
    }
    __syncthreads();

    // ---- phase 2: warp q -> dual softmax over row q; write transposed ----
    {
        const int q = warp;
        const bool v0 = (lane      < nk);
        const bool v1 = (lane + 32 < nk);
        const bool v2 = (lane + 64 < nk);
        const float t0 = v0 ? (at2[0][lane     ][q] + at2[1][lane     ][q]) * scale : 0.0f;
        const float t1 = v1 ? (at2[0][lane + 32][q] + at2[1][lane + 32][q]) * scale : 0.0f;
        const float t2 = v2 ? (at2[0][lane + 64][q] + at2[1][lane + 64][q]) * scale : 0.0f;

        float mx = -1e30f, mn = 1e30f;
        if (v0) { mx = fmaxf(mx, t0); mn = fminf(mn, t0); }
        if (v1) { mx = fmaxf(mx, t1); mn = fminf(mn, t1); }
        if (v2) { mx = fmaxf(mx, t2); mn = fminf(mn, t2); }
        #pragma unroll
        for (int o = 16; o; o >>= 1) {
            mx = fmaxf(mx, __shfl_xor_sync(0xffffffffu, mx, o));
            mn = fminf(mn, __shfl_xor_sync(0xffffffffu, mn, o));
        }

        float sp = 0.0f, sn = 0.0f;
        float e0p=0, e0n=0, e1p=0, e1n=0, e2p=0, e2n=0;
        if (v0) { e0p = __expf(t0 - mx); e0n = __expf(mn - t0); sp += e0p; sn += e0n; }
        if (v1) { e1p = __expf(t1 - mx); e1n = __expf(mn - t1); sp += e1p; sn += e1n; }
        if (v2) { e2p = __expf(t2 - mx); e2n = __expf(mn - t2); sp += e2p; sn += e2n; }
        #pragma unroll
        for (int o = 16; o; o >>= 1) {
            sp += __shfl_xor_sync(0xffffffffu, sp, o);
            sn += __shfl_xor_sync(0xffffffffu, sn, o);
        }
        const float rp = 1.0f / sp;
        const float rn = 1.0f / sn;
        if (v0) at_t[q][lane     ] = e0p * rp - e0n * rn;
        if (v1) at_t[q][lane + 32] = e1p * rp - e1n * rn;
        if (v2) at_t[q][lane + 64] = e2p * rp - e2n * rn;
    }
    cp_wait0();                            // V ready
    __syncthreads();

    // ---- phase 3: key-halves x 16-wide d-slices; A read as float4/4keys ----
    {
        const int w4   = warp & 3;
        const int q    = lane >> 2;                     // 0..7
        const int dof  = w4 * 16 + (lane & 3) * 4;      // float4 slice
        const int half = nk >> 1;                       // multiple of 4
        const int j0   = (warp >= 4) ? half : 0;
        const int j1   = j0 + half;

        float4 acc = make_float4(0.f, 0.f, 0.f, 0.f);
        for (int j = j0; j < j1; j += 4) {
            const float4 a4 = *(const float4*)&at_t[q][j];   // 8 quads, CF: 1 wf
            float4 vv;
            vv = *(const float4*)&vs[j + 0][dof];
            acc.x = fmaf(a4.x, vv.x, acc.x); acc.y = fmaf(a4.x, vv.y, acc.y);
            acc.z = fmaf(a4.x, vv.z, acc.z); acc.w = fmaf(a4.x, vv.w, acc.w);
            vv = *(const float4*)&vs[j + 1][dof];
            acc.x = fmaf(a4.y, vv.x, acc.x); acc.y = fmaf(a4.y, vv.y, acc.y);
            acc.z = fmaf(a4.y, vv.z, acc.z); acc.w = fmaf(a4.y, vv.w, acc.w);
            vv = *(const float4*)&vs[j + 2][dof];
            acc.x = fmaf(a4.z, vv.x, acc.x); acc.y = fmaf(a4.z, vv.y, acc.y);
            acc.z = fmaf(a4.z, vv.z, acc.z); acc.w = fmaf(a4.z, vv.w, acc.w);
            vv = *(const float4*)&vs[j + 3][dof];
            acc.x = fmaf(a4.w, vv.x, acc.x); acc.y = fmaf(a4.w, vv.y, acc.y);
            acc.z = fmaf(a4.w, vv.z, acc.z); acc.w = fmaf(a4.w, vv.w, acc.w);
        }
        if (warp >= 4)
            *(float4*)&part[q][dof] = acc;
        __syncthreads();
        if (warp < 4) {
            const float4 pp = *(const float4*)&part[q][dof];
            acc.x += pp.x; acc.y += pp.y; acc.z += pp.z; acc.w += pp.w;
            *(float4*)(O + qbase + (size_t)q * Dv + dof) = acc;
        }
    }
}

extern "C" void kernel_launch(void* const* d_in, const int* in_sizes, int n_in,
                              void* d_out, int out_size)
{
    const float* Q  = (const float*)d_in[0];
    const float* K  = (const float*)d_in[1];
    const float* V  = (const float*)d_in[2];
    const float* LS = (const float*)d_in[3];
    float* O = (float*)d_out;

    const int BH = in_sizes[0] / (Lv * Dv);   // B*H = 32
    signed_attn_kernel<<<BH * NP, NT>>>(Q, K, V, LS, O);
}

// round 6
// speedup vs baseline: 1.6760x; 1.0506x over previous
#include <cuda_runtime.h>
#include <cstdint>

// SignedAttention R6: occupancy push. V smem eliminated (single-use -> direct
// LDG.128 in phase 3, L2-hot), single score buffer, 5 CTAs/SM (40 warps).

constexpr int Lv   = 1024;
constexpr int Dv   = 64;
constexpr int NP   = 128;
constexpr int CH   = 8;
constexpr int MAXK = 72;
constexpr int KP   = 76;   // K pitch: quad stride 19 -> conflict-free row reads
constexpr int AP   = 9;    // score pitch: gcd(9,32)=1 -> CF scalar access
constexpr int TP   = 76;   // at_t pitch: 12q mod 32 distinct -> CF quad reads
constexpr int NT   = 256;

__device__ __forceinline__ void cp16(void* dst, const void* src) {
    uint32_t d = (uint32_t)__cvta_generic_to_shared(dst);
    asm volatile("cp.async.cg.shared.global [%0], [%1], 16;" :: "r"(d), "l"(src));
}
__device__ __forceinline__ void cp_commit() { asm volatile("cp.async.commit_group;"); }
__device__ __forceinline__ void cp_wait0()  { asm volatile("cp.async.wait_group 0;"); }

__global__ __launch_bounds__(NT, 5)
void signed_attn_kernel(const float* __restrict__ Q,
                        const float* __restrict__ K,
                        const float* __restrict__ V,
                        const float* __restrict__ LS,
                        float* __restrict__ O)
{
    __shared__ float qs[CH][Dv];           // 2 KB
    __shared__ float ks[MAXK][KP];         // 21.4 KB
    __shared__ float at[MAXK][AP];         // 2.5 KB : scaled scores, [key][q]
    __shared__ float at_t[CH][TP];         // 2.4 KB : weights, [q][key]
    __shared__ float part[CH][Dv];         // 2 KB  : phase-3 partials
                                           // total ~30.3 KB -> 5+ CTAs/SM

    const int bh   = blockIdx.x / NP;
    const int p    = blockIdx.x % NP;
    const int tid  = threadIdx.x;
    const int warp = tid >> 5;
    const int lane = tid & 31;

    const size_t qbase = ((size_t)bh * Lv + (size_t)p * CH) * Dv;

    const int npk = min(9, NP - 1 - p);
    const int nk  = npk * CH;              // multiple of 8, 0..72

    if (nk == 0) {                         // last patch: A == 0 exactly
        O[qbase + tid]      = 0.0f;
        O[qbase + tid + NT] = 0.0f;
        return;
    }

    // ---- stage Q + K via cp.async (V is NOT staged) ----
    const size_t kbase = ((size_t)bh * Lv + (size_t)(p + 1) * CH) * Dv;
    const int n4 = nk * (Dv / 4);
    {
        if (tid < (CH * Dv) / 4) {
            int r = tid >> 4, c = tid & 15;
            cp16(&qs[r][c * 4], (const float4*)(Q + qbase) + tid);
        }
        const float4* Kg = (const float4*)(K + kbase);
        for (int idx = tid; idx < n4; idx += NT) {
            int r = idx >> 4, c = idx & 15;
            cp16(&ks[r][c * 4], Kg + idx);
        }
        cp_commit();
    }

    const float scale = fminf(fmaxf(expf(LS[0]), 1.0f), 30.0f) * 0.125f;

    cp_wait0();
    __syncthreads();

    // ---- phase 1: 3 warps, lane = key j, full-d accumulate for 8 queries ----
    if (warp < 3) {
        const int j = warp * 32 + lane;
        if (j < nk) {
            float acc[CH] = {0,0,0,0,0,0,0,0};
            #pragma unroll
            for (int dd = 0; dd < Dv / 4; dd++) {
                const float4 kf = *(const float4*)&ks[j][dd * 4];
                #pragma unroll
                for (int qi = 0; qi < CH; qi++) {
                    const float4 qf = *(const float4*)&qs[qi][dd * 4];
                    acc[qi] = fmaf(qf.x, kf.x, acc[qi]);
                    acc[qi] = fmaf(qf.y, kf.y, acc[qi]);
                    acc[qi] = fmaf(qf.z, kf.z, acc[qi]);
                    acc[qi] = fmaf(qf.w, kf.w, acc[qi]);
                }
            }
            #pragma unroll
            for (int qi = 0; qi < CH; qi++)
                at[j][qi] = acc[qi] * scale;            // pitch-9: CF
        }
    }
    __syncthreads();

    // ---- phase 2: warp q -> dual softmax over row q; write transposed ----
    {
        const int q = warp;
        const bool v0 = (lane      < nk);
        const bool v1 = (lane + 32 < nk);
        const bool v2 = (lane + 64 < nk);
        const float t0 = v0 ? at[lane     ][q] : 0.0f;
        const float t1 = v1 ? at[lane + 32][q] : 0.0f;
        const float t2 = v2 ? at[lane + 64][q] : 0.0f;

        float mx = -1e30f, mn = 1e30f;
        if (v0) { mx = fmaxf(mx, t0); mn = fminf(mn, t0); }
        if (v1) { mx = fmaxf(mx, t1); mn = fminf(mn, t1); }
        if (v2) { mx = fmaxf(mx, t2); mn = fminf(mn, t2); }
        #pragma unroll
        for (int o = 16; o; o >>= 1) {
            mx = fmaxf(mx, __shfl_xor_sync(0xffffffffu, mx, o));
            mn = fminf(mn, __shfl_xor_sync(0xffffffffu, mn, o));
        }

        float sp = 0.0f, sn = 0.0f;
        float e0p=0, e0n=0, e1p=0, e1n=0, e2p=0, e2n=0;
        if (v0) { e0p = __expf(t0 - mx); e0n = __expf(mn - t0); sp += e0p; sn += e0n; }
        if (v1) { e1p = __expf(t1 - mx); e1n = __expf(mn - t1); sp += e1p; sn += e1n; }
        if (v2) { e2p = __expf(t2 - mx); e2n = __expf(mn - t2); sp += e2p; sn += e2n; }
        #pragma unroll
        for (int o = 16; o; o >>= 1) {
            sp += __shfl_xor_sync(0xffffffffu, sp, o);
            sn += __shfl_xor_sync(0xffffffffu, sn, o);
        }
        const float rp = 1.0f / sp;
        const float rn = 1.0f / sn;
        if (v0) at_t[q][lane     ] = e0p * rp - e0n * rn;
        if (v1) at_t[q][lane + 32] = e1p * rp - e1n * rn;
        if (v2) at_t[q][lane + 64] = e2p * rp - e2n * rn;
    }
    __syncthreads();

    // ---- phase 3: key-halves x 16-wide d-slices; V via direct LDG.128 ----
    {
        const int w4   = warp & 3;
        const int q    = lane >> 2;                     // 0..7
        const int dof  = w4 * 16 + (lane & 3) * 4;      // float4 slice
        const int half = nk >> 1;                       // multiple of 4
        const int j0   = (warp >= 4) ? half : 0;
        const int j1   = j0 + half;

        const float4* __restrict__ Vg =
            (const float4*)(V + kbase + dof) + (size_t)j0 * (Dv / 4);

        float4 acc = make_float4(0.f, 0.f, 0.f, 0.f);
        #pragma unroll 4
        for (int j = j0; j < j1; j += 4) {
            const float4 a4 = *(const float4*)&at_t[q][j];   // CF quad read
            float4 vv;
            vv = Vg[0 * (Dv / 4)];
            acc.x = fmaf(a4.x, vv.x, acc.x); acc.y = fmaf(a4.x, vv.y, acc.y);
            acc.z = fmaf(a4.x, vv.z, acc.z); acc.w = fmaf(a4.x, vv.w, acc.w);
            vv = Vg[1 * (Dv / 4)];
            acc.x = fmaf(a4.y, vv.x, acc.x); acc.y = fmaf(a4.y, vv.y, acc.y);
            acc.z = fmaf(a4.y, vv.z, acc.z); acc.w = fmaf(a4.y, vv.w, acc.w);
            vv = Vg[2 * (Dv / 4)];
            acc.x = fmaf(a4.z, vv.x, acc.x); acc.y = fmaf(a4.z, vv.y, acc.y);
            acc.z = fmaf(a4.z, vv.z, acc.z); acc.w = fmaf(a4.z, vv.w, acc.w);
            vv = Vg[3 * (Dv / 4)];
            acc.x = fmaf(a4.w, vv.x, acc.x); acc.y = fmaf(a4.w, vv.y, acc.y);
            acc.z = fmaf(a4.w, vv.z, acc.z); acc.w = fmaf(a4.w, vv.w, acc.w);
            Vg += 4 * (Dv / 4);
        }
        if (warp >= 4)
            *(float4*)&part[q][dof] = acc;
        __syncthreads();
        if (warp < 4) {
            const float4 pp = *(const float4*)&part[q][dof];
            acc.x += pp.x; acc.y += pp.y; acc.z += pp.z; acc.w += pp.w;
            *(float4*)(O + qbase + (size_t)q * Dv + dof) = acc;
        }
    }
}

extern "C" void kernel_launch(void* const* d_in, const int* in_sizes, int n_in,
                              void* d_out, int out_size)
{
    const float* Q  = (const float*)d_in[0];
    const float* K  = (const float*)d_in[1];
    const float* V  = (const float*)d_in[2];
    const float* LS = (const float*)d_in[3];
    float* O = (float*)d_out;

    const int BH = in_sizes[0] / (Lv * Dv);   // B*H = 32
    signed_attn_kernel<<<BH * NP, NT>>>(Q, K, V, LS, O);
}